// round 8
// baseline (speedup 1.0000x reference)
#include <cuda_runtime.h>

// SNN forward: B=128, T=1000, F=20, H=256, O=200.
// 1 CTA per batch element, 1024 threads, layer-pipelined persistent loop:
// iteration t -> layer1 step t, layer2 step t-1, readout step t-2.
// Single gather phase (V1/W2T/V2/WoT concurrent, 4 warp-bands) + 2 full barriers.
// Gather: spike lists hold BYTE offsets, pairwise LDS.64, packed f32x2 adds.

#define Bt 128
#define Tt 1000
#define Ft 20
#define Ht 256
#define Ot 200
#define NTHR 1024
#define ROWB 1024              // bytes per weight row (256 floats)
#define ZOFF (256 * ROWB)      // byte offset of the shared zero row

// Weights padded to 257 rows x 256 floats (row 256 = zeros for list padding).
__device__ __align__(16) float g_V1[257 * 256];
__device__ __align__(16) float g_V2[257 * 256];
__device__ __align__(16) float g_W2T[257 * 256];   // W2T[h][g] = W2[g][h]
__device__ __align__(16) float g_WoT[257 * 256];   // WoT[h][o] = Wout[o][h], cols 200..255 = 0
__device__ float g_Wx1[(size_t)Tt * Bt * Ht];      // precomputed x@W1^T + b1, [t*B+b][h]

__global__ void snn_prep(const float* __restrict__ V1, const float* __restrict__ V2,
                         const float* __restrict__ W2, const float* __restrict__ Wout) {
    int i = blockIdx.x * blockDim.x + threadIdx.x;
    if (i >= 257 * 256) return;
    int r = i >> 8, c = i & 255;
    if (r < 256) {
        float z = (r == c) ? 0.0f : 1.0f;
        g_V1[i]  = V1[r * 256 + c] * z;
        g_V2[i]  = V2[r * 256 + c] * z;
        g_W2T[i] = W2[c * 256 + r];
        g_WoT[i] = (c < Ot) ? Wout[c * 256 + r] : 0.0f;
    } else {
        g_V1[i] = 0.f; g_V2[i] = 0.f; g_W2T[i] = 0.f; g_WoT[i] = 0.f;
    }
}

// Pre-GEMM: Wx1[tb][h] = sum_f x[b][t][f] * W1[h][f] + b1[h], tb = t*Bt + b.
__global__ __launch_bounds__(256) void snn_wx(const float* __restrict__ x,
                                              const float* __restrict__ W1,
                                              const float* __restrict__ b1) {
    __shared__ float xs[16][Ft];
    const int tb0 = blockIdx.x * 16;
    const int tid = threadIdx.x;
    for (int i = tid; i < 16 * Ft; i += 256) {
        int pr = i / Ft, f = i - pr * Ft;
        int tb = tb0 + pr;
        int t = tb >> 7, bb = tb & 127;
        xs[pr][f] = x[((size_t)bb * Tt + t) * Ft + f];
    }
    __syncthreads();
    float w[Ft];
    #pragma unroll
    for (int f = 0; f < Ft; f++) w[f] = W1[tid * Ft + f];
    const float bb1 = b1[tid];
    #pragma unroll
    for (int pr = 0; pr < 16; pr++) {
        float a0 = bb1, a1 = 0.f, a2 = 0.f, a3 = 0.f;
        #pragma unroll
        for (int f = 0; f < 5; f++) {
            a0 = fmaf(xs[pr][f],      w[f],      a0);
            a1 = fmaf(xs[pr][f + 5],  w[f + 5],  a1);
            a2 = fmaf(xs[pr][f + 10], w[f + 10], a2);
            a3 = fmaf(xs[pr][f + 15], w[f + 15], a3);
        }
        g_Wx1[(size_t)(tb0 + pr) * Ht + tid] = (a0 + a1) + (a2 + a3);
    }
}

// SMEM layout (float index):
#define OFF_PA   0        // [4*256] V1 partials
#define OFF_PC   1024     // [4*256] W2T partials
#define OFF_PB   2048     // [4*256] V2 partials
#define OFF_PW   3072     // [4*256] WoT partials
#define OFF_L1   4096     // [2*256] int: ping-pong byte-offset list layer1
#define OFF_L2   4608     // [2*256] int: ping-pong byte-offset list layer2
#define OFF_WC1  5120     // [8] int
#define OFF_WC2  5128     // [8] int
#define OFF_NC   5136     // [4] int: n1[2], n2[2]
#define OFF_WRM  5140     // [8] softmax max scratch
#define OFF_WRS  5148     // [8] softmax sum scratch
#define SMEM_FLOATS 5156
#define SMEM_BYTES  (SMEM_FLOATS * 4)

#define BSYNC(id, n) asm volatile("bar.sync %0, %1;" :: "r"(id), "r"(n) : "memory")
#define ADDX2(d, a, b) asm("add.rn.f32x2 %0, %1, %2;" : "=l"(d) : "l"(a), "l"(b))

__global__ __launch_bounds__(NTHR, 1)
void snn_main(const float* __restrict__ b2v, const float* __restrict__ beta2v,
              const float* __restrict__ alpha_out, const float* __restrict__ beta_out,
              const float* __restrict__ beta1v,
              float* __restrict__ out) {
    extern __shared__ float sm[];
    float* PA  = sm + OFF_PA;
    float* PC  = sm + OFF_PC;
    float* PB  = sm + OFF_PB;
    float* PW  = sm + OFF_PW;
    int*   l1  = (int*)(sm + OFF_L1);
    int*   l2  = (int*)(sm + OFF_L2);
    int*   wc1 = (int*)(sm + OFF_WC1);
    int*   wc2 = (int*)(sm + OFF_WC2);
    int*   nc  = (int*)(sm + OFF_NC);
    float* wrm = sm + OFF_WRM;
    float* wrs = sm + OFF_WRS;

    const int tid  = threadIdx.x;
    const int b    = blockIdx.x;
    const int grp  = tid >> 6;              // 0..15
    const int g    = grp & 3;               // group within matrix band
    const int mat  = grp >> 2;              // 0:V1 1:W2T 2:V2 3:WoT
    const int lg   = tid & 63;
    const int wid  = tid >> 5, lane = tid & 31;

    if (tid < 4) nc[tid] = 0;

    float syn1 = 0.f, mem1 = 0.f, spk1 = 0.f;
    float syn2 = 0.f, mem2 = 0.f, spk2 = 0.f;
    float synO = 0.f, memO = 0.f, spkO = 0.f, accO = 0.f;
    float be1 = 0.f, b2r = 0.f, be2 = 0.f, aOr = 0.f, bOr = 0.f;
    const int h2 = tid - 256;               // layer2 neuron index (warps 8-15)
    const int oo = tid - 512;               // output index (warps 16-22)
    if (tid < Ht)           be1 = beta1v[tid];
    if (h2 >= 0 && h2 < Ht) { b2r = b2v[h2]; be2 = beta2v[h2]; }
    if (oo >= 0 && oo < Ot) { aOr = alpha_out[oo]; bOr = beta_out[oo]; }

    float wx_cur = (tid < Ht) ? __ldg(&g_Wx1[(size_t)b * Ht + tid]) : 0.f;
    __syncthreads();

    for (int t = 0; t <= Tt + 1; t++) {
        const int p = t & 1, q = p ^ 1;

        // prefetch next-step input drive (consumed next iteration)
        float wx_nxt = 0.f;
        if (tid < Ht && t + 1 < Tt)
            wx_nxt = __ldg(&g_Wx1[(size_t)((t + 1) * Bt + b) * Ht + tid]);

        // ---- single gather phase: byte-offset lists, pairwise, f32x2 adds ----
        if (mat == 0) {               // V1 rows over l1[q] -> PA
            if (t < Tt) {
                const int n = nc[q];
                const int* lst = l1 + q * 256;
                const char* base = (const char*)g_V1 + 16 * lg;
                unsigned long long a0 = 0ull, a1 = 0ull;
                #pragma unroll 4
                for (int j = 2 * g; j < n; j += 8) {
                    int2 ij = *(const int2*)(lst + j);
                    ulonglong2 v0 = __ldg((const ulonglong2*)(base + ij.x));
                    ulonglong2 v1 = __ldg((const ulonglong2*)(base + ij.y));
                    ADDX2(a0, a0, v0.x); ADDX2(a1, a1, v0.y);
                    ADDX2(a0, a0, v1.x); ADDX2(a1, a1, v1.y);
                }
                ulonglong2 r; r.x = a0; r.y = a1;
                *(ulonglong2*)(PA + g * 256 + 4 * lg) = r;
            }
        } else if (mat == 1) {        // W2T rows over l1[q] -> PC
            if (t >= 1 && t <= Tt) {
                const int n = nc[q];
                const int* lst = l1 + q * 256;
                const char* base = (const char*)g_W2T + 16 * lg;
                unsigned long long a0 = 0ull, a1 = 0ull;
                #pragma unroll 4
                for (int j = 2 * g; j < n; j += 8) {
                    int2 ij = *(const int2*)(lst + j);
                    ulonglong2 v0 = __ldg((const ulonglong2*)(base + ij.x));
                    ulonglong2 v1 = __ldg((const ulonglong2*)(base + ij.y));
                    ADDX2(a0, a0, v0.x); ADDX2(a1, a1, v0.y);
                    ADDX2(a0, a0, v1.x); ADDX2(a1, a1, v1.y);
                }
                ulonglong2 r; r.x = a0; r.y = a1;
                *(ulonglong2*)(PC + g * 256 + 4 * lg) = r;
            }
        } else if (mat == 2) {        // V2 rows over l2[q] -> PB
            if (t >= 1 && t <= Tt) {
                const int n = nc[2 + q];
                const int* lst = l2 + q * 256;
                const char* base = (const char*)g_V2 + 16 * lg;
                unsigned long long a0 = 0ull, a1 = 0ull;
                #pragma unroll 4
                for (int j = 2 * g; j < n; j += 8) {
                    int2 ij = *(const int2*)(lst + j);
                    ulonglong2 v0 = __ldg((const ulonglong2*)(base + ij.x));
                    ulonglong2 v1 = __ldg((const ulonglong2*)(base + ij.y));
                    ADDX2(a0, a0, v0.x); ADDX2(a1, a1, v0.y);
                    ADDX2(a0, a0, v1.x); ADDX2(a1, a1, v1.y);
                }
                ulonglong2 r; r.x = a0; r.y = a1;
                *(ulonglong2*)(PB + g * 256 + 4 * lg) = r;
            }
        } else {                      // WoT rows (first 200 cols) over l2[q] -> PW
            if (t >= 2 && lg < 50) {
                const int n = nc[2 + q];
                const int* lst = l2 + q * 256;
                const char* base = (const char*)g_WoT + 16 * lg;
                unsigned long long a0 = 0ull, a1 = 0ull;
                #pragma unroll 4
                for (int j = 2 * g; j < n; j += 8) {
                    int2 ij = *(const int2*)(lst + j);
                    ulonglong2 v0 = __ldg((const ulonglong2*)(base + ij.x));
                    ulonglong2 v1 = __ldg((const ulonglong2*)(base + ij.y));
                    ADDX2(a0, a0, v0.x); ADDX2(a1, a1, v0.y);
                    ADDX2(a0, a0, v1.x); ADDX2(a1, a1, v1.y);
                }
                ulonglong2 r; r.x = a0; r.y = a1;
                *(ulonglong2*)(PW + g * 256 + 4 * lg) = r;
            }
        }
        __syncthreads();                                        // S1

        // ---- layer1 step t (warps 0-7) ----
        if (wid < 8) {
            if (t < Tt) {
                float s = ((PA[tid] + PA[256 + tid]) + (PA[512 + tid] + PA[768 + tid]));
                syn1 = 0.95f * syn1 + (wx_cur + s);
                mem1 = be1 * mem1 + syn1 - spk1;                // THR=1, detached reset
                spk1 = (mem1 - 1.0f) > 0.f ? 1.f : 0.f;

                unsigned bal = __ballot_sync(0xffffffffu, spk1 != 0.f);
                if (lane == 0) wc1[wid] = __popc(bal);
                BSYNC(1, 256);
                int off = 0, tot = 0;
                #pragma unroll
                for (int w = 0; w < 8; w++) { int c = wc1[w]; off += (w < wid) ? c : 0; tot += c; }
                if (spk1 != 0.f)
                    l1[p * 256 + off + __popc(bal & ((1u << lane) - 1u))] = tid << 10;
                if (tid == tot) l1[p * 256 + tot] = ZOFF;       // pair-loop padding
                if (tid == 0) nc[p] = tot;
            }
        }
        // ---- layer2 step t-1 (warps 8-15) ----
        else if (wid < 16) {
            if (t >= 1 && t <= Tt) {
                const int w2 = wid - 8;
                float s = ((PC[h2] + PC[256 + h2]) + (PC[512 + h2] + PC[768 + h2])) +
                          ((PB[h2] + PB[256 + h2]) + (PB[512 + h2] + PB[768 + h2]));
                syn2 = 0.95f * syn2 + (b2r + s);
                mem2 = be2 * mem2 + syn2 - spk2;
                spk2 = (mem2 - 1.0f) > 0.f ? 1.f : 0.f;

                unsigned bal = __ballot_sync(0xffffffffu, spk2 != 0.f);
                if (lane == 0) wc2[w2] = __popc(bal);
                BSYNC(3, 256);
                int off = 0, tot = 0;
                #pragma unroll
                for (int w = 0; w < 8; w++) { int c = wc2[w]; off += (w < w2) ? c : 0; tot += c; }
                if (spk2 != 0.f)
                    l2[p * 256 + off + __popc(bal & ((1u << lane) - 1u))] = h2 << 10;
                if (h2 == tot) l2[p * 256 + tot] = ZOFF;
                if (h2 == 0) nc[2 + p] = tot;
            }
        }
        // ---- readout step t-2 (warps 16-22) ----
        else if (wid < 23) {
            if (t >= 2) {
                float mval = -3.402823e38f;
                if (oo < Ot) {
                    float o_t = ((PW[oo] + PW[256 + oo]) + (PW[512 + oo] + PW[768 + oo]));
                    synO = aOr * synO + o_t;
                    memO = bOr * memO + synO - spkO;
                    spkO = (memO - 1.0f) > 0.f ? 1.f : 0.f;
                    mval = memO;
                }
                #pragma unroll
                for (int sh = 16; sh; sh >>= 1)
                    mval = fmaxf(mval, __shfl_xor_sync(0xffffffffu, mval, sh));
                if (lane == 0) wrm[wid - 16] = mval;
                BSYNC(2, 224);
                float mx = fmaxf(fmaxf(fmaxf(wrm[0], wrm[1]), fmaxf(wrm[2], wrm[3])),
                                 fmaxf(fmaxf(wrm[4], wrm[5]), wrm[6]));
                float ev = (oo < Ot) ? __expf(memO - mx) : 0.f;
                float sv = ev;
                #pragma unroll
                for (int sh = 16; sh; sh >>= 1)
                    sv += __shfl_xor_sync(0xffffffffu, sv, sh);
                if (lane == 0) wrs[wid - 16] = sv;
                BSYNC(2, 224);
                float ssum = (((wrs[0] + wrs[1]) + (wrs[2] + wrs[3])) +
                              ((wrs[4] + wrs[5]) + wrs[6]));
                if (oo < Ot && t > 12) accO += __fdividef(ev, ssum);  // step t-2 > WARMUP
            }
        }
        wx_cur = wx_nxt;
        __syncthreads();                                        // S2
    }

    if (oo >= 0 && oo < Ot) out[b * Ot + oo] = accO;
}

extern "C" void kernel_launch(void* const* d_in, const int* in_sizes, int n_in,
                              void* d_out, int out_size) {
    const float* x         = (const float*)d_in[0];
    const float* W1        = (const float*)d_in[1];
    const float* b1        = (const float*)d_in[2];
    const float* Vrec1     = (const float*)d_in[3];
    const float* beta1     = (const float*)d_in[4];
    const float* W2        = (const float*)d_in[5];
    const float* b2        = (const float*)d_in[6];
    const float* Vrec2     = (const float*)d_in[7];
    const float* beta2     = (const float*)d_in[8];
    const float* Wout      = (const float*)d_in[9];
    const float* alpha_out = (const float*)d_in[10];
    const float* beta_out  = (const float*)d_in[11];
    float* out = (float*)d_out;

    cudaFuncSetAttribute((const void*)snn_main,
                         cudaFuncAttributeMaxDynamicSharedMemorySize, SMEM_BYTES);

    snn_prep<<<(257 * 256 + 255) / 256, 256>>>(Vrec1, Vrec2, W2, Wout);
    snn_wx<<<(Tt * Bt) / 16, 256>>>(x, W1, b1);
    snn_main<<<Bt, NTHR, SMEM_BYTES>>>(b2, beta2, alpha_out, beta_out, beta1, out);
}

// round 9
// speedup vs baseline: 1.4042x; 1.4042x over previous
#include <cuda_runtime.h>

// SNN forward: B=128, T=1000, F=20, H=256, O=200.
// 1 CTA per batch element, 1024 threads, persistent loop.
// LAYER-PIPELINED (R6 structure): iteration t -> layer1 step t, layer2 step t-1,
// readout step t-2; single gather phase (V1/W2T/V2/WoT concurrent) + 2 barriers.
// R9 change: gather accumulation uses packed add.rn.f32x2 (2 ops per 16B, not 4).

#define Bt 128
#define Tt 1000
#define Ft 20
#define Ht 256
#define Ot 200
#define NTHR 1024

// Preprocessed weights (diag-zeroed Vrec, transposed W2/Wout), L2-resident (~968KB).
__device__ __align__(16) float g_V1[Ht * Ht];
__device__ __align__(16) float g_V2[Ht * Ht];
__device__ __align__(16) float g_W2T[Ht * Ht];   // W2T[h][g] = W2[g][h]
__device__ __align__(16) float g_WoT[Ht * Ot];   // WoT[h][o] = Wout[o][h]

__global__ void snn_prep(const float* __restrict__ V1, const float* __restrict__ V2,
                         const float* __restrict__ W2, const float* __restrict__ Wout) {
    int i = blockIdx.x * blockDim.x + threadIdx.x;
    if (i < Ht * Ht) {
        int r = i >> 8, c = i & 255;
        float z = (r == c) ? 0.0f : 1.0f;
        g_V1[i] = V1[i] * z;
        g_V2[i] = V2[i] * z;
        g_W2T[i] = W2[c * Ht + r];
    }
    if (i < Ht * Ot) {
        int h = i / Ot, o = i - h * Ot;
        g_WoT[i] = Wout[o * Ht + h];
    }
}

// Dynamic SMEM layout (float index):
#define OFF_W1T  0        // [5120]  W1 transposed [F][H]
#define OFF_PA   5120     // [4*256] V1  partials
#define OFF_PC   6144     // [4*256] W2T partials
#define OFF_PB   7168     // [4*256] V2  partials
#define OFF_PW   8192     // [4*256] WoT partials
#define OFF_L1   9216     // [512] int: ping-pong spike list layer1
#define OFF_L2   9728     // [512] int: ping-pong spike list layer2
#define OFF_WC1  10240    // [8]   int
#define OFF_WC2  10248    // [8]   int
#define OFF_NCNT 10256    // [4]   int: n1[2], n2[2]
#define OFF_WRM  10260    // [8]   softmax max scratch
#define OFF_WRS  10268    // [8]   softmax sum scratch
#define OFF_XBUF 10276    // [2*20] x(t) double buffer
#define SMEM_FLOATS (10276 + 40)
#define SMEM_BYTES  (SMEM_FLOATS * 4)

#define NB1() asm volatile("bar.sync 1, 256;" ::: "memory")   // warps 0-7   (layer1)
#define NB2() asm volatile("bar.sync 3, 256;" ::: "memory")   // warps 8-15  (layer2)
#define NB3() asm volatile("bar.sync 2, 224;" ::: "memory")   // warps 16-22 (readout)
#define ADDX2(d, a, b) asm("add.rn.f32x2 %0, %1, %2;" : "=l"(d) : "l"(a), "l"(b))

__global__ __launch_bounds__(NTHR, 1)
void snn_main(const float* __restrict__ x, const float* __restrict__ W1,
              const float* __restrict__ b1, const float* __restrict__ beta1,
              const float* __restrict__ b2, const float* __restrict__ beta2,
              const float* __restrict__ alpha_out, const float* __restrict__ beta_out,
              float* __restrict__ out) {
    extern __shared__ float sm[];
    float* w1t  = sm + OFF_W1T;
    float* PA   = sm + OFF_PA;
    float* PC   = sm + OFF_PC;
    float* PB   = sm + OFF_PB;
    float* PW   = sm + OFF_PW;
    int*   l1   = (int*)(sm + OFF_L1);
    int*   l2   = (int*)(sm + OFF_L2);
    int*   wc1  = (int*)(sm + OFF_WC1);
    int*   wc2  = (int*)(sm + OFF_WC2);
    int*   ncnt = (int*)(sm + OFF_NCNT);
    float* wrm  = sm + OFF_WRM;
    float* wrs  = sm + OFF_WRS;
    float* xbuf = sm + OFF_XBUF;

    const int tid  = threadIdx.x;
    const int b    = blockIdx.x;
    const int grp  = tid >> 6;              // 0..15 (64-thread row groups)
    const int g    = grp & 3;               // group within matrix
    const int mat  = grp >> 2;              // 0:V1 1:W2T 2:V2 3:WoT
    const int lg   = tid & 63;              // float4 column within row
    const int wid  = tid >> 5, lane = tid & 31;
    const float* xb = x + (size_t)b * (Tt * Ft);

    for (int i = tid; i < Ft * Ht; i += NTHR) {       // W1^T [F][H]
        int f = i >> 8, h = i & 255;
        w1t[i] = W1[h * Ft + f];
    }
    if (tid < 4) ncnt[tid] = 0;
    if (tid < Ft) xbuf[tid] = __ldg(xb + tid);        // x(0) -> slot 0

    // Role state: layer1 on tid 0-255, layer2 on 256-511, readout on 512-711.
    float syn1 = 0.f, mem1 = 0.f, spk1 = 0.f;
    float syn2 = 0.f, mem2 = 0.f, spk2 = 0.f;
    float synO = 0.f, memO = 0.f, spkO = 0.f, accO = 0.f;
    float b1r = 0.f, be1 = 0.f, b2r = 0.f, be2 = 0.f, aOr = 0.f, bOr = 0.f;
    const int h2 = tid - 256;                         // layer2 neuron index
    const int oo = tid - 512;                         // output neuron index
    if (tid < Ht)              { b1r = b1[tid]; be1 = beta1[tid]; }
    if (h2 >= 0 && h2 < Ht)    { b2r = b2[h2];  be2 = beta2[h2]; }
    if (oo >= 0 && oo < Ot)    { aOr = alpha_out[oo]; bOr = beta_out[oo]; }
    __syncthreads();

    // Iteration t: layer1 step t (t<Tt), layer2 step t-1 (1<=t<=Tt),
    // readout step t-2 (2<=t<=Tt+1). Gathers read parity q, updates write p.
    for (int t = 0; t <= Tt + 1; t++) {
        const int p = t & 1, q = p ^ 1;
        const int n1o = ncnt[q];        // |spk1(t-1)|
        const int n2o = ncnt[2 + q];    // |spk2(t-2)|

        float xnext = 0.f;
        if (tid < Ft && t + 1 < Tt) xnext = __ldg(xb + (t + 1) * Ft + tid);

        // ---- single gather phase: 4 matrices concurrently, packed f32x2 adds ----
        if (mat == 0) {               // V1 rows over l1[q] -> PA
            if (t < Tt) {
                const float* base = g_V1 + 4 * lg;
                const int*   lst  = l1 + q * 256;
                unsigned long long a0 = 0ull, a1 = 0ull;
                #pragma unroll 8
                for (int j = g; j < n1o; j += 4) {
                    ulonglong2 v = __ldg((const ulonglong2*)(base + (lst[j] << 8)));
                    ADDX2(a0, a0, v.x); ADDX2(a1, a1, v.y);
                }
                ulonglong2 r; r.x = a0; r.y = a1;
                *(ulonglong2*)(PA + g * 256 + 4 * lg) = r;
            }
        } else if (mat == 1) {        // W2T rows over l1[q] -> PC
            if (t >= 1 && t <= Tt) {
                const float* base = g_W2T + 4 * lg;
                const int*   lst  = l1 + q * 256;
                unsigned long long a0 = 0ull, a1 = 0ull;
                #pragma unroll 8
                for (int j = g; j < n1o; j += 4) {
                    ulonglong2 v = __ldg((const ulonglong2*)(base + (lst[j] << 8)));
                    ADDX2(a0, a0, v.x); ADDX2(a1, a1, v.y);
                }
                ulonglong2 r; r.x = a0; r.y = a1;
                *(ulonglong2*)(PC + g * 256 + 4 * lg) = r;
            }
        } else if (mat == 2) {        // V2 rows over l2[q] -> PB
            if (t >= 1 && t <= Tt) {
                const float* base = g_V2 + 4 * lg;
                const int*   lst  = l2 + q * 256;
                unsigned long long a0 = 0ull, a1 = 0ull;
                #pragma unroll 8
                for (int j = g; j < n2o; j += 4) {
                    ulonglong2 v = __ldg((const ulonglong2*)(base + (lst[j] << 8)));
                    ADDX2(a0, a0, v.x); ADDX2(a1, a1, v.y);
                }
                ulonglong2 r; r.x = a0; r.y = a1;
                *(ulonglong2*)(PB + g * 256 + 4 * lg) = r;
            }
        } else {                      // WoT rows (200 wide) over l2[q] -> PW
            if (t >= 2 && lg < 50) {
                const float* base = g_WoT + 4 * lg;
                const int*   lst  = l2 + q * 256;
                unsigned long long a0 = 0ull, a1 = 0ull;
                #pragma unroll 8
                for (int j = g; j < n2o; j += 4) {
                    ulonglong2 v = __ldg((const ulonglong2*)(base + lst[j] * Ot));
                    ADDX2(a0, a0, v.x); ADDX2(a1, a1, v.y);
                }
                ulonglong2 r; r.x = a0; r.y = a1;
                *(ulonglong2*)(PW + g * 256 + 4 * lg) = r;
            }
        }
        __syncthreads();                                        // S1
        if (tid < Ft && t + 1 < Tt) xbuf[q * Ft + tid] = xnext;

        // ---- layer1 step t (warps 0-7) ----
        if (t < Tt && tid < Ht) {
            const float* xt = xbuf + p * Ft;
            float a0 = b1r, a1 = 0.f, a2 = 0.f, a3 = 0.f;
            #pragma unroll
            for (int f = 0; f < 5; f++) {
                a0 = fmaf(xt[f],      w1t[f * Ht + tid],        a0);
                a1 = fmaf(xt[f + 5],  w1t[(f + 5) * Ht + tid],  a1);
                a2 = fmaf(xt[f + 10], w1t[(f + 10) * Ht + tid], a2);
                a3 = fmaf(xt[f + 15], w1t[(f + 15) * Ht + tid], a3);
            }
            float wx = (a0 + a1) + (a2 + a3);
            float s = ((PA[tid] + PA[256 + tid]) + (PA[512 + tid] + PA[768 + tid]));
            syn1 = 0.95f * syn1 + (wx + s);
            mem1 = be1 * mem1 + syn1 - spk1;                    // THR=1, detached reset
            spk1 = (mem1 - 1.0f) > 0.f ? 1.f : 0.f;

            unsigned bal = __ballot_sync(0xffffffffu, spk1 != 0.f);
            if (lane == 0) wc1[wid] = __popc(bal);
            NB1();
            int off = 0, tot = 0;
            #pragma unroll
            for (int w = 0; w < 8; w++) { int c = wc1[w]; off += (w < wid) ? c : 0; tot += c; }
            if (spk1 != 0.f) l1[p * 256 + off + __popc(bal & ((1u << lane) - 1u))] = tid;
            if (tid == 0) ncnt[p] = tot;
        }

        // ---- layer2 step t-1 (warps 8-15) ----
        if (t >= 1 && t <= Tt && h2 >= 0 && h2 < Ht) {
            const int w2 = wid - 8;
            float s = ((PC[h2] + PC[256 + h2]) + (PC[512 + h2] + PC[768 + h2])) +
                      ((PB[h2] + PB[256 + h2]) + (PB[512 + h2] + PB[768 + h2]));
            syn2 = 0.95f * syn2 + (b2r + s);
            mem2 = be2 * mem2 + syn2 - spk2;
            spk2 = (mem2 - 1.0f) > 0.f ? 1.f : 0.f;

            unsigned bal = __ballot_sync(0xffffffffu, spk2 != 0.f);
            if (lane == 0) wc2[w2] = __popc(bal);
            NB2();
            int off = 0, tot = 0;
            #pragma unroll
            for (int w = 0; w < 8; w++) { int c = wc2[w]; off += (w < w2) ? c : 0; tot += c; }
            if (spk2 != 0.f) l2[p * 256 + off + __popc(bal & ((1u << lane) - 1u))] = h2;
            if (h2 == 0) ncnt[2 + p] = tot;
        }

        // ---- readout step t-2 (warps 16-22), 2 named barriers ----
        if (t >= 2 && wid >= 16 && wid < 23) {
            float mval = -3.402823e38f;
            if (oo < Ot) {
                float o_t = ((PW[oo] + PW[256 + oo]) + (PW[512 + oo] + PW[768 + oo]));
                synO = aOr * synO + o_t;
                memO = bOr * memO + synO - spkO;
                spkO = (memO - 1.0f) > 0.f ? 1.f : 0.f;
                mval = memO;
            }
            #pragma unroll
            for (int s = 16; s; s >>= 1) mval = fmaxf(mval, __shfl_xor_sync(0xffffffffu, mval, s));
            if (lane == 0) wrm[wid - 16] = mval;
            NB3();
            float mx = fmaxf(fmaxf(fmaxf(wrm[0], wrm[1]), fmaxf(wrm[2], wrm[3])),
                             fmaxf(fmaxf(wrm[4], wrm[5]), wrm[6]));
            float ev = (oo < Ot) ? __expf(memO - mx) : 0.f;
            float sv = ev;
            #pragma unroll
            for (int s = 16; s; s >>= 1) sv += __shfl_xor_sync(0xffffffffu, sv, s);
            if (lane == 0) wrs[wid - 16] = sv;
            NB3();
            float ssum = (((wrs[0] + wrs[1]) + (wrs[2] + wrs[3])) +
                          ((wrs[4] + wrs[5]) + wrs[6]));
            if (oo < Ot && t > 12) accO += __fdividef(ev, ssum);  // step (t-2) > WARMUP
        }
        __syncthreads();                                        // S2
    }

    if (oo >= 0 && oo < Ot) out[b * Ot + oo] = accO;
}

extern "C" void kernel_launch(void* const* d_in, const int* in_sizes, int n_in,
                              void* d_out, int out_size) {
    const float* x         = (const float*)d_in[0];
    const float* W1        = (const float*)d_in[1];
    const float* b1        = (const float*)d_in[2];
    const float* Vrec1     = (const float*)d_in[3];
    const float* beta1     = (const float*)d_in[4];
    const float* W2        = (const float*)d_in[5];
    const float* b2        = (const float*)d_in[6];
    const float* Vrec2     = (const float*)d_in[7];
    const float* beta2     = (const float*)d_in[8];
    const float* Wout      = (const float*)d_in[9];
    const float* alpha_out = (const float*)d_in[10];
    const float* beta_out  = (const float*)d_in[11];
    float* out = (float*)d_out;

    cudaFuncSetAttribute((const void*)snn_main,
                         cudaFuncAttributeMaxDynamicSharedMemorySize, SMEM_BYTES);

    snn_prep<<<(Ht * Ht + 255) / 256, 256>>>(Vrec1, Vrec2, W2, Wout);
    snn_main<<<Bt, NTHR, SMEM_BYTES>>>(x, W1, b1, beta1, b2, beta2,
                                       alpha_out, beta_out, out);
}

// round 10
// speedup vs baseline: 1.6683x; 1.1880x over previous
#include <cuda_runtime.h>

// SNN forward: B=128, T=1000, F=20, H=256, O=200.
// 1 CTA per batch element, 1024 threads, persistent loop.
// LAYER-PIPELINED (R6/R9 structure): iteration t -> layer1 step t, layer2 step t-1,
// readout step t-2; single gather phase (V1/W2T/V2/WoT concurrent) + 2 barriers.
// R10 change: spike lists padded to multiple of 4 with a zero-row id; gather
// consumes 4 consecutive ids per iteration via one LDS.128 (int4), 4 independent
// LDG.128s, packed f32x2 accumulation into split even/odd accumulators.

#define Bt 128
#define Tt 1000
#define Ft 20
#define Ht 256
#define Ot 200
#define NTHR 1024
#define ZID 256                 // id of the all-zero padding row

// Preprocessed weights, 257 rows (row 256 = zeros), L2-resident (~1MB).
__device__ __align__(16) float g_V1[257 * 256];
__device__ __align__(16) float g_V2[257 * 256];
__device__ __align__(16) float g_W2T[257 * 256];   // W2T[h][g] = W2[g][h]
__device__ __align__(16) float g_WoT[257 * 200];   // WoT[h][o] = Wout[o][h]

__global__ void snn_prep(const float* __restrict__ V1, const float* __restrict__ V2,
                         const float* __restrict__ W2, const float* __restrict__ Wout) {
    int i = blockIdx.x * blockDim.x + threadIdx.x;
    if (i < 257 * 256) {
        int r = i >> 8, c = i & 255;
        if (r < 256) {
            float z = (r == c) ? 0.0f : 1.0f;
            g_V1[i]  = V1[r * 256 + c] * z;
            g_V2[i]  = V2[r * 256 + c] * z;
            g_W2T[i] = W2[c * 256 + r];
        } else {
            g_V1[i] = 0.f; g_V2[i] = 0.f; g_W2T[i] = 0.f;
        }
    }
    if (i < 257 * 200) {
        int h = i / 200, o = i - h * 200;
        g_WoT[i] = (h < 256) ? Wout[o * 256 + h] : 0.f;
    }
}

// Dynamic SMEM layout (float index):
#define OFF_W1T  0        // [5120]  W1 transposed [F][H]
#define OFF_PA   5120     // [4*256] V1  partials
#define OFF_PC   6144     // [4*256] W2T partials
#define OFF_PB   7168     // [4*256] V2  partials
#define OFF_PW   8192     // [4*256] WoT partials
#define OFF_L1   9216     // [2*260] int: ping-pong padded spike list layer1
#define OFF_L2   9736     // [2*260] int: ping-pong padded spike list layer2
#define OFF_WC1  10256    // [8]   int
#define OFF_WC2  10264    // [8]   int
#define OFF_NCNT 10272    // [4]   int: n1[2], n2[2]
#define OFF_WRM  10276    // [8]   softmax max scratch
#define OFF_WRS  10284    // [8]   softmax sum scratch
#define OFF_XBUF 10292    // [2*20] x(t) double buffer
#define SMEM_FLOATS (10292 + 40)
#define SMEM_BYTES  (SMEM_FLOATS * 4)

#define NB1() asm volatile("bar.sync 1, 256;" ::: "memory")   // warps 0-7   (layer1)
#define NB2() asm volatile("bar.sync 3, 256;" ::: "memory")   // warps 8-15  (layer2)
#define NB3() asm volatile("bar.sync 2, 224;" ::: "memory")   // warps 16-22 (readout)
#define ADDX2(d, a, b) asm("add.rn.f32x2 %0, %1, %2;" : "=l"(d) : "l"(a), "l"(b))

// Gather 4 consecutive ids (one int4 block) from `base` rows of `stride` floats.
#define GATHER4(ptr, stride)                                                    \
    do {                                                                        \
        ulonglong2 v0 = __ldg((const ulonglong2*)((ptr) + e.x * (stride)));     \
        ulonglong2 v1 = __ldg((const ulonglong2*)((ptr) + e.y * (stride)));     \
        ulonglong2 v2 = __ldg((const ulonglong2*)((ptr) + e.z * (stride)));     \
        ulonglong2 v3 = __ldg((const ulonglong2*)((ptr) + e.w * (stride)));     \
        ADDX2(s0, s0, v0.x); ADDX2(s1, s1, v0.y);                               \
        ADDX2(s2, s2, v1.x); ADDX2(s3, s3, v1.y);                               \
        ADDX2(s0, s0, v2.x); ADDX2(s1, s1, v2.y);                               \
        ADDX2(s2, s2, v3.x); ADDX2(s3, s3, v3.y);                               \
    } while (0)

__global__ __launch_bounds__(NTHR, 1)
void snn_main(const float* __restrict__ x, const float* __restrict__ W1,
              const float* __restrict__ b1, const float* __restrict__ beta1,
              const float* __restrict__ b2, const float* __restrict__ beta2,
              const float* __restrict__ alpha_out, const float* __restrict__ beta_out,
              float* __restrict__ out) {
    extern __shared__ float sm[];
    float* w1t  = sm + OFF_W1T;
    float* PA   = sm + OFF_PA;
    float* PC   = sm + OFF_PC;
    float* PB   = sm + OFF_PB;
    float* PW   = sm + OFF_PW;
    int*   l1   = (int*)(sm + OFF_L1);
    int*   l2   = (int*)(sm + OFF_L2);
    int*   wc1  = (int*)(sm + OFF_WC1);
    int*   wc2  = (int*)(sm + OFF_WC2);
    int*   ncnt = (int*)(sm + OFF_NCNT);
    float* wrm  = sm + OFF_WRM;
    float* wrs  = sm + OFF_WRS;
    float* xbuf = sm + OFF_XBUF;

    const int tid  = threadIdx.x;
    const int b    = blockIdx.x;
    const int grp  = tid >> 6;              // 0..15 (64-thread row groups)
    const int g    = grp & 3;               // group within matrix
    const int mat  = grp >> 2;              // 0:V1 1:W2T 2:V2 3:WoT
    const int lg   = tid & 63;              // float4 column within row
    const int wid  = tid >> 5, lane = tid & 31;
    const float* xb = x + (size_t)b * (Tt * Ft);

    for (int i = tid; i < Ft * Ht; i += NTHR) {       // W1^T [F][H]
        int f = i >> 8, h = i & 255;
        w1t[i] = W1[h * Ft + f];
    }
    if (tid < 4) ncnt[tid] = 0;
    if (tid < Ft) xbuf[tid] = __ldg(xb + tid);        // x(0) -> slot 0

    // Role state: layer1 on tid 0-255, layer2 on 256-511, readout on 512-711.
    float syn1 = 0.f, mem1 = 0.f, spk1 = 0.f;
    float syn2 = 0.f, mem2 = 0.f, spk2 = 0.f;
    float synO = 0.f, memO = 0.f, spkO = 0.f, accO = 0.f;
    float b1r = 0.f, be1 = 0.f, b2r = 0.f, be2 = 0.f, aOr = 0.f, bOr = 0.f;
    const int h2 = tid - 256;                         // layer2 neuron index
    const int oo = tid - 512;                         // output neuron index
    if (tid < Ht)              { b1r = b1[tid]; be1 = beta1[tid]; }
    if (h2 >= 0 && h2 < Ht)    { b2r = b2[h2];  be2 = beta2[h2]; }
    if (oo >= 0 && oo < Ot)    { aOr = alpha_out[oo]; bOr = beta_out[oo]; }
    __syncthreads();

    // Iteration t: layer1 step t (t<Tt), layer2 step t-1 (1<=t<=Tt),
    // readout step t-2 (2<=t<=Tt+1). Gathers read parity q, updates write p.
    for (int t = 0; t <= Tt + 1; t++) {
        const int p = t & 1, q = p ^ 1;
        const int nB1o = (ncnt[q] + 3) >> 2;      // int4 blocks in l1[q]
        const int nB2o = (ncnt[2 + q] + 3) >> 2;  // int4 blocks in l2[q]

        float xnext = 0.f;
        if (tid < Ft && t + 1 < Tt) xnext = __ldg(xb + (t + 1) * Ft + tid);

        // ---- single gather phase: 4 matrices concurrently, int4 list blocks ----
        if (mat == 0) {               // V1 rows over l1[q] -> PA
            if (t < Tt) {
                const float* base = g_V1 + 4 * lg;
                const int4* lst4 = (const int4*)(l1 + q * 260);
                unsigned long long s0 = 0ull, s1 = 0ull, s2 = 0ull, s3 = 0ull;
                #pragma unroll 2
                for (int k = g; k < nB1o; k += 4) {
                    int4 e = lst4[k];
                    GATHER4(base, 256);
                }
                ulonglong2 r; ADDX2(r.x, s0, s2); ADDX2(r.y, s1, s3);
                *(ulonglong2*)(PA + g * 256 + 4 * lg) = r;
            }
        } else if (mat == 1) {        // W2T rows over l1[q] -> PC
            if (t >= 1 && t <= Tt) {
                const float* base = g_W2T + 4 * lg;
                const int4* lst4 = (const int4*)(l1 + q * 260);
                unsigned long long s0 = 0ull, s1 = 0ull, s2 = 0ull, s3 = 0ull;
                #pragma unroll 2
                for (int k = g; k < nB1o; k += 4) {
                    int4 e = lst4[k];
                    GATHER4(base, 256);
                }
                ulonglong2 r; ADDX2(r.x, s0, s2); ADDX2(r.y, s1, s3);
                *(ulonglong2*)(PC + g * 256 + 4 * lg) = r;
            }
        } else if (mat == 2) {        // V2 rows over l2[q] -> PB
            if (t >= 1 && t <= Tt) {
                const float* base = g_V2 + 4 * lg;
                const int4* lst4 = (const int4*)(l2 + q * 260);
                unsigned long long s0 = 0ull, s1 = 0ull, s2 = 0ull, s3 = 0ull;
                #pragma unroll 2
                for (int k = g; k < nB2o; k += 4) {
                    int4 e = lst4[k];
                    GATHER4(base, 256);
                }
                ulonglong2 r; ADDX2(r.x, s0, s2); ADDX2(r.y, s1, s3);
                *(ulonglong2*)(PB + g * 256 + 4 * lg) = r;
            }
        } else {                      // WoT rows (200 wide) over l2[q] -> PW
            if (t >= 2 && lg < 50) {
                const float* base = g_WoT + 4 * lg;
                const int4* lst4 = (const int4*)(l2 + q * 260);
                unsigned long long s0 = 0ull, s1 = 0ull, s2 = 0ull, s3 = 0ull;
                #pragma unroll 2
                for (int k = g; k < nB2o; k += 4) {
                    int4 e = lst4[k];
                    GATHER4(base, 200);
                }
                ulonglong2 r; ADDX2(r.x, s0, s2); ADDX2(r.y, s1, s3);
                *(ulonglong2*)(PW + g * 256 + 4 * lg) = r;
            }
        }
        __syncthreads();                                        // S1
        if (tid < Ft && t + 1 < Tt) xbuf[q * Ft + tid] = xnext;

        // ---- layer1 step t (warps 0-7) ----
        if (t < Tt && tid < Ht) {
            const float* xt = xbuf + p * Ft;
            float a0 = b1r, a1 = 0.f, a2 = 0.f, a3 = 0.f;
            #pragma unroll
            for (int f = 0; f < 5; f++) {
                a0 = fmaf(xt[f],      w1t[f * Ht + tid],        a0);
                a1 = fmaf(xt[f + 5],  w1t[(f + 5) * Ht + tid],  a1);
                a2 = fmaf(xt[f + 10], w1t[(f + 10) * Ht + tid], a2);
                a3 = fmaf(xt[f + 15], w1t[(f + 15) * Ht + tid], a3);
            }
            float wx = (a0 + a1) + (a2 + a3);
            float s = ((PA[tid] + PA[256 + tid]) + (PA[512 + tid] + PA[768 + tid]));
            syn1 = 0.95f * syn1 + (wx + s);
            mem1 = be1 * mem1 + syn1 - spk1;                    // THR=1, detached reset
            spk1 = (mem1 - 1.0f) > 0.f ? 1.f : 0.f;

            unsigned bal = __ballot_sync(0xffffffffu, spk1 != 0.f);
            if (lane == 0) wc1[wid] = __popc(bal);
            NB1();
            int off = 0, tot = 0;
            #pragma unroll
            for (int w = 0; w < 8; w++) { int c = wc1[w]; off += (w < wid) ? c : 0; tot += c; }
            if (spk1 != 0.f) l1[p * 260 + off + __popc(bal & ((1u << lane) - 1u))] = tid;
            if (tid >= tot && tid < tot + 4) l1[p * 260 + tid] = ZID;  // pad block
            if (tid == 0) ncnt[p] = tot;
        }

        // ---- layer2 step t-1 (warps 8-15) ----
        if (t >= 1 && t <= Tt && h2 >= 0 && h2 < Ht) {
            const int w2 = wid - 8;
            float s = ((PC[h2] + PC[256 + h2]) + (PC[512 + h2] + PC[768 + h2])) +
                      ((PB[h2] + PB[256 + h2]) + (PB[512 + h2] + PB[768 + h2]));
            syn2 = 0.95f * syn2 + (b2r + s);
            mem2 = be2 * mem2 + syn2 - spk2;
            spk2 = (mem2 - 1.0f) > 0.f ? 1.f : 0.f;

            unsigned bal = __ballot_sync(0xffffffffu, spk2 != 0.f);
            if (lane == 0) wc2[w2] = __popc(bal);
            NB2();
            int off = 0, tot = 0;
            #pragma unroll
            for (int w = 0; w < 8; w++) { int c = wc2[w]; off += (w < w2) ? c : 0; tot += c; }
            if (spk2 != 0.f) l2[p * 260 + off + __popc(bal & ((1u << lane) - 1u))] = h2;
            if (h2 >= tot && h2 < tot + 4) l2[p * 260 + h2] = ZID;    // pad block
            if (h2 == 0) ncnt[2 + p] = tot;
        }

        // ---- readout step t-2 (warps 16-22), 2 named barriers ----
        if (t >= 2 && wid >= 16 && wid < 23) {
            float mval = -3.402823e38f;
            if (oo < Ot) {
                float o_t = ((PW[oo] + PW[256 + oo]) + (PW[512 + oo] + PW[768 + oo]));
                synO = aOr * synO + o_t;
                memO = bOr * memO + synO - spkO;
                spkO = (memO - 1.0f) > 0.f ? 1.f : 0.f;
                mval = memO;
            }
            #pragma unroll
            for (int s = 16; s; s >>= 1) mval = fmaxf(mval, __shfl_xor_sync(0xffffffffu, mval, s));
            if (lane == 0) wrm[wid - 16] = mval;
            NB3();
            float mx = fmaxf(fmaxf(fmaxf(wrm[0], wrm[1]), fmaxf(wrm[2], wrm[3])),
                             fmaxf(fmaxf(wrm[4], wrm[5]), wrm[6]));
            float ev = (oo < Ot) ? __expf(memO - mx) : 0.f;
            float sv = ev;
            #pragma unroll
            for (int s = 16; s; s >>= 1) sv += __shfl_xor_sync(0xffffffffu, sv, s);
            if (lane == 0) wrs[wid - 16] = sv;
            NB3();
            float ssum = (((wrs[0] + wrs[1]) + (wrs[2] + wrs[3])) +
                          ((wrs[4] + wrs[5]) + wrs[6]));
            if (oo < Ot && t > 12) accO += __fdividef(ev, ssum);  // step (t-2) > WARMUP
        }
        __syncthreads();                                        // S2
    }

    if (oo >= 0 && oo < Ot) out[b * Ot + oo] = accO;
}

extern "C" void kernel_launch(void* const* d_in, const int* in_sizes, int n_in,
                              void* d_out, int out_size) {
    const float* x         = (const float*)d_in[0];
    const float* W1        = (const float*)d_in[1];
    const float* b1        = (const float*)d_in[2];
    const float* Vrec1     = (const float*)d_in[3];
    const float* beta1     = (const float*)d_in[4];
    const float* W2        = (const float*)d_in[5];
    const float* b2        = (const float*)d_in[6];
    const float* Vrec2     = (const float*)d_in[7];
    const float* beta2     = (const float*)d_in[8];
    const float* Wout      = (const float*)d_in[9];
    const float* alpha_out = (const float*)d_in[10];
    const float* beta_out  = (const float*)d_in[11];
    float* out = (float*)d_out;

    cudaFuncSetAttribute((const void*)snn_main,
                         cudaFuncAttributeMaxDynamicSharedMemorySize, SMEM_BYTES);

    snn_prep<<<(257 * 256 + 255) / 256, 256>>>(Vrec1, Vrec2, W2, Wout);
    snn_main<<<Bt, NTHR, SMEM_BYTES>>>(x, W1, b1, beta1, b2, beta2,
                                       alpha_out, beta_out, out);
}